// round 11
// baseline (speedup 1.0000x reference)
#include <cuda_runtime.h>
#include <cuda_fp16.h>
#include <math.h>

#define NMAX 100000
#define EMAX 1000000
#define F    64
#define FO   16
#define NBIN 64

// ---------------- scratch (no allocations allowed) ----------------
__device__ int    g_hist[NMAX];
__device__ int    g_rank[EMAX];
__device__ int    g_rowptr[NMAX + 1];
__device__ int2   g_colw[EMAX];          // packed (col, w-bits)
__device__ float  g_dinv[NMAX];
__device__ int    g_noderank[NMAX];      // rank within degree bin
__device__ int    g_binCnt[NBIN];
__device__ int    g_binStart[NBIN];
__device__ int    g_perm[NMAX];          // nodes sorted by degree
__device__ __half g_bufH1[(size_t)NMAX * F];
__device__ __half g_bufH2[(size_t)NMAX * F];
__device__ float  g_buf16[(size_t)NMAX * FO];
__device__ int    g_part[1024];

// ---------------- x (fp32) -> fp16, plus zeroing of hist/binCnt --------------
__global__ void k_cvt(const float* __restrict__ x, __half* __restrict__ dst,
                      int total4, int nNodes) {
    int i = blockIdx.x * blockDim.x + threadIdx.x;
    if (i < NBIN) g_binCnt[i] = 0;
    if (i < nNodes) g_hist[i] = 0;
    if (i >= total4) return;
    float4 v = ((const float4*)x)[i];
    __half2 lo = __floats2half2_rn(v.x, v.y);
    __half2 hi = __floats2half2_rn(v.z, v.w);
    uint2 u;
    u.x = *(unsigned*)&lo; u.y = *(unsigned*)&hi;
    ((uint2*)dst)[i] = u;
}

// ---------------- CSR build ----------------
// histogram + per-edge rank in one atomic pass
__global__ void k_hist_rank(const int* __restrict__ ei, int E) {
    int e = blockIdx.x * blockDim.x + threadIdx.x;
    if (e < E) g_rank[e] = atomicAdd(&g_hist[ei[e]], 1);
}

// block-local exclusive scan (1024 threads) + dinv + degree-bin count
__global__ void k_scan_block(int n) {
    __shared__ int sh[1024];
    int gid = blockIdx.x * 1024 + threadIdx.x;
    int v = (gid < n) ? g_hist[gid] : 0;
    if (gid < n) {
        g_dinv[gid] = rsqrtf((float)v + 1.0f);   // +1 self loop
        int bin = v < NBIN - 1 ? v : NBIN - 1;
        g_noderank[gid] = atomicAdd(&g_binCnt[bin], 1);
    }
    sh[threadIdx.x] = v;
    __syncthreads();
    #pragma unroll
    for (int off = 1; off < 1024; off <<= 1) {
        int t = (threadIdx.x >= off) ? sh[threadIdx.x - off] : 0;
        __syncthreads();
        sh[threadIdx.x] += t;
        __syncthreads();
    }
    if (gid < n) g_rowptr[gid] = sh[threadIdx.x] - v;     // exclusive
    if (threadIdx.x == 1023) g_part[blockIdx.x] = sh[1023];
}

// add sum of partials below this block; block 0 also scans the degree bins
__global__ void k_scan_add(int n, int Etot) {
    __shared__ int sred[1024];
    if (blockIdx.x == 0 && threadIdx.x == 0) {
        int run = 0;
        #pragma unroll
        for (int b = 0; b < NBIN; b++) { int t = g_binCnt[b]; g_binStart[b] = run; run += t; }
    }
    int v = (threadIdx.x < blockIdx.x) ? g_part[threadIdx.x] : 0;
    sred[threadIdx.x] = v;
    __syncthreads();
    #pragma unroll
    for (int off = 512; off >= 1; off >>= 1) {
        if (threadIdx.x < off) sred[threadIdx.x] += sred[threadIdx.x + off];
        __syncthreads();
    }
    int base = sred[0];
    int gid = blockIdx.x * 1024 + threadIdx.x;
    if (gid < n) g_rowptr[gid] += base;
    if (gid == 0) g_rowptr[n] = Etot;
}

// atomic-free fill + node permutation scatter (first n threads)
__global__ void k_fill(const int* __restrict__ ei, int E, int n) {
    int e = blockIdx.x * blockDim.x + threadIdx.x;
    if (e < n) {
        int deg = g_hist[e];
        int bin = deg < NBIN - 1 ? deg : NBIN - 1;
        g_perm[g_binStart[bin] + g_noderank[e]] = e;
    }
    if (e >= E) return;
    int r = ei[e];
    int c = ei[E + e];
    int pos = g_rowptr[r] + g_rank[e];
    float w = g_dinv[r] * g_dinv[c];
    g_colw[pos] = make_int2(c, __float_as_int(w));
}

// ---------------- fp16 SpMM core: 8 lanes/node, 8 features per lane ----------
__device__ __forceinline__ void h8_acc(uint4 u, float w, float* acc) {
    __half2* h = (__half2*)&u;
    float2 f0 = __half22float2(h[0]);
    float2 f1 = __half22float2(h[1]);
    float2 f2 = __half22float2(h[2]);
    float2 f3 = __half22float2(h[3]);
    acc[0] += w * f0.x; acc[1] += w * f0.y;
    acc[2] += w * f1.x; acc[3] += w * f1.y;
    acc[4] += w * f2.x; acc[5] += w * f2.y;
    acc[6] += w * f3.x; acc[7] += w * f3.y;
}

__device__ __forceinline__ void spmm_row_h(const __half* __restrict__ src, int node,
                                           int l8, float* acc) {
    float d  = g_dinv[node];
    float sw = d * d;
    #pragma unroll
    for (int i = 0; i < 8; i++) acc[i] = 0.f;
    h8_acc(((const uint4*)(src + (size_t)node * F))[l8], sw, acc);
    int s = g_rowptr[node], e = g_rowptr[node + 1];
    int p = s;
    for (; p + 8 <= e; p += 8) {
        int jj[8]; float ww[8];
        #pragma unroll
        for (int q = 0; q < 8; q++) {
            int2 cw = g_colw[p + q];
            jj[q] = cw.x; ww[q] = __int_as_float(cw.y);
        }
        uint4 vv[8];
        #pragma unroll
        for (int q = 0; q < 8; q++)
            vv[q] = ((const uint4*)(src + (size_t)jj[q] * F))[l8];
        #pragma unroll
        for (int q = 0; q < 8; q++)
            h8_acc(vv[q], ww[q], acc);
    }
    if (p + 4 <= e) {
        int jj[4]; float ww[4];
        #pragma unroll
        for (int q = 0; q < 4; q++) {
            int2 cw = g_colw[p + q];
            jj[q] = cw.x; ww[q] = __int_as_float(cw.y);
        }
        uint4 vv[4];
        #pragma unroll
        for (int q = 0; q < 4; q++)
            vv[q] = ((const uint4*)(src + (size_t)jj[q] * F))[l8];
        #pragma unroll
        for (int q = 0; q < 4; q++)
            h8_acc(vv[q], ww[q], acc);
        p += 4;
    }
    for (; p < e; p++) {
        int2 cw = g_colw[p];
        uint4 v = ((const uint4*)(src + (size_t)cw.x * F))[l8];
        h8_acc(v, __int_as_float(cw.y), acc);
    }
}

__device__ __forceinline__ uint4 f8_to_h8(const float* acc) {
    __half2 h0 = __floats2half2_rn(acc[0], acc[1]);
    __half2 h1 = __floats2half2_rn(acc[2], acc[3]);
    __half2 h2 = __floats2half2_rn(acc[4], acc[5]);
    __half2 h3 = __floats2half2_rn(acc[6], acc[7]);
    uint4 u;
    u.x = *(unsigned*)&h0; u.y = *(unsigned*)&h1;
    u.z = *(unsigned*)&h2; u.w = *(unsigned*)&h3;
    return u;
}

__global__ void k_spmm_h(const __half* __restrict__ src, __half* __restrict__ dst, int n) {
    int tid  = blockIdx.x * blockDim.x + threadIdx.x;
    int g    = tid >> 3;
    int l8   = tid & 7;
    if (g >= n) return;
    int node = g_perm[g];               // degree-sorted order: uniform warp workload
    float acc[8];
    spmm_row_h(src, node, l8, acc);
    ((uint4*)(dst + (size_t)node * F))[l8] = f8_to_h8(acc);
}

// ---------------- hop4 fused: fp16 SpMM + W1 + SELU + W2 -> N x 16 -----------
#define PAD 4
__global__ void k_hop4_fused(const __half* __restrict__ src, float* __restrict__ dst16,
                             const float* __restrict__ W1, const float* __restrict__ b1,
                             const float* __restrict__ W2, const float* __restrict__ b2, int n) {
    __shared__ float W1s[F * F];
    __shared__ float W2s[F * FO];
    __shared__ float b2s[FO];
    __shared__ float y_s[32][F + PAD];
    __shared__ float h_s[32][F + PAD];
    for (int t = threadIdx.x; t < F * F; t += blockDim.x) W1s[t] = W1[t];
    for (int t = threadIdx.x; t < F * FO; t += blockDim.x) W2s[t] = W2[t];
    if (threadIdx.x < FO) b2s[threadIdx.x] = b2[threadIdx.x];
    __syncthreads();

    int nodeL = threadIdx.x >> 3;
    int l8    = threadIdx.x & 7;
    int g     = blockIdx.x * 32 + nodeL;
    int node  = (g < n) ? g_perm[g] : -1;

    float acc[8];
    #pragma unroll
    for (int i = 0; i < 8; i++) acc[i] = 0.f;
    if (node >= 0) spmm_row_h(src, node, l8, acc);
    ((float4*)&y_s[nodeL][8 * l8])[0]     = make_float4(acc[0], acc[1], acc[2], acc[3]);
    ((float4*)&y_s[nodeL][8 * l8 + 4])[0] = make_float4(acc[4], acc[5], acc[6], acc[7]);
    __syncwarp();

    // GEMM1 + SELU: lane l8 computes features l8 + 8*m, m=0..7
    float h[8];
    #pragma unroll
    for (int m = 0; m < 8; m++) h[m] = b1[l8 + 8 * m];
    #pragma unroll 8
    for (int k = 0; k < F; k++) {
        float yk = y_s[nodeL][k];
        #pragma unroll
        for (int m = 0; m < 8; m++)
            h[m] += yk * W1s[k * F + l8 + 8 * m];
    }
    const float al = 1.6732632423543772f, sc = 1.0507009873554805f;
    #pragma unroll
    for (int m = 0; m < 8; m++) {
        h[m] = (h[m] > 0.f) ? sc * h[m] : sc * al * expm1f(h[m]);
        h_s[nodeL][l8 + 8 * m] = h[m];
    }
    __syncwarp();

    // GEMM2: lane l8 computes output features l8 and l8+8
    float z0 = b2s[l8], z1 = b2s[l8 + 8];
    #pragma unroll 8
    for (int k = 0; k < F; k++) {
        float hk = h_s[nodeL][k];
        z0 += hk * W2s[k * FO + l8];
        z1 += hk * W2s[k * FO + l8 + 8];
    }
    if (node >= 0) {
        dst16[(size_t)node * FO + l8]     = z0;
        dst16[(size_t)node * FO + l8 + 8] = z1;
    }
}

// ---------------- final 16-wide hop + log_softmax: 4 lanes/node, float4 -------
__global__ void k_hop16(const float* __restrict__ src16, float* __restrict__ out, int n) {
    int tid  = blockIdx.x * blockDim.x + threadIdx.x;
    int g    = tid >> 2;
    int l4   = tid & 3;
    if (g >= n) return;
    int node = g_perm[g];
    float d = g_dinv[node];
    float sw = d * d;
    float4 a = ((const float4*)(src16 + (size_t)node * FO))[l4];
    float4 acc = make_float4(sw * a.x, sw * a.y, sw * a.z, sw * a.w);
    int s = g_rowptr[node], e = g_rowptr[node + 1];
    int p = s;
    for (; p + 4 <= e; p += 4) {
        int jj[4]; float ww[4];
        #pragma unroll
        for (int q = 0; q < 4; q++) {
            int2 cw = g_colw[p + q];
            jj[q] = cw.x; ww[q] = __int_as_float(cw.y);
        }
        float4 v0 = ((const float4*)(src16 + (size_t)jj[0] * FO))[l4];
        float4 v1 = ((const float4*)(src16 + (size_t)jj[1] * FO))[l4];
        float4 v2 = ((const float4*)(src16 + (size_t)jj[2] * FO))[l4];
        float4 v3 = ((const float4*)(src16 + (size_t)jj[3] * FO))[l4];
        acc.x += ww[0] * v0.x + ww[1] * v1.x + ww[2] * v2.x + ww[3] * v3.x;
        acc.y += ww[0] * v0.y + ww[1] * v1.y + ww[2] * v2.y + ww[3] * v3.y;
        acc.z += ww[0] * v0.z + ww[1] * v1.z + ww[2] * v2.z + ww[3] * v3.z;
        acc.w += ww[0] * v0.w + ww[1] * v1.w + ww[2] * v2.w + ww[3] * v3.w;
    }
    for (; p < e; p++) {
        int2 cw = g_colw[p];
        float w = __int_as_float(cw.y);
        float4 v = ((const float4*)(src16 + (size_t)cw.x * FO))[l4];
        acc.x += w * v.x; acc.y += w * v.y; acc.z += w * v.z; acc.w += w * v.w;
    }

    float m = fmaxf(fmaxf(acc.x, acc.y), fmaxf(acc.z, acc.w));
    m = fmaxf(m, __shfl_xor_sync(0xffffffffu, m, 1, 4));
    m = fmaxf(m, __shfl_xor_sync(0xffffffffu, m, 2, 4));
    float ssum = expf(acc.x - m) + expf(acc.y - m) + expf(acc.z - m) + expf(acc.w - m);
    ssum += __shfl_xor_sync(0xffffffffu, ssum, 1, 4);
    ssum += __shfl_xor_sync(0xffffffffu, ssum, 2, 4);
    float lse = m + logf(ssum);
    float4 r = make_float4(acc.x - lse, acc.y - lse, acc.z - lse, acc.w - lse);
    ((float4*)(out + (size_t)node * FO))[l4] = r;
}

// ---------------- launch ----------------
extern "C" void kernel_launch(void* const* d_in, const int* in_sizes, int n_in,
                              void* d_out, int out_size) {
    const float* x  = (const float*)d_in[0];
    const float* W1 = (const float*)d_in[1];
    const float* b1 = (const float*)d_in[2];
    const float* W2 = (const float*)d_in[3];
    const float* b2 = (const float*)d_in[4];
    const int*   ei = (const int*)  d_in[5];
    int N = in_sizes[0] / F;
    int E = in_sizes[5] / 2;
    float* out = (float*)d_out;

    __half *H1, *H2;
    float  *buf16;
    cudaGetSymbolAddress((void**)&H1, g_bufH1);
    cudaGetSymbolAddress((void**)&H2, g_bufH2);
    cudaGetSymbolAddress((void**)&buf16, g_buf16);

    int tb = 256;
    int nbE    = (E + tb - 1) / tb;
    int nb1024 = (N + 1023) / 1024;
    int nbC    = (N * F / 4 + tb - 1) / tb;    // convert: float4 per thread (covers N and NBIN zeroing)
    int nb8    = (N * 8 + tb - 1) / tb;        // 8 lanes/node
    int nbF    = (N + 31) / 32;                // hop4 fused: 32 nodes/block
    int nbQ    = (N * 4 + tb - 1) / tb;        // 4 lanes/node

    // cvt first: also zeroes g_hist and g_binCnt
    k_cvt       <<<nbC, tb>>>(x, H1, N * F / 4, N);
    // CSR build (rank-based fill) + degree-sort permutation (folded)
    k_hist_rank <<<nbE, tb>>>(ei, E);
    k_scan_block<<<nb1024, 1024>>>(N);
    k_scan_add  <<<nb1024, 1024>>>(N, E);
    k_fill      <<<nbE, tb>>>(ei, E, N);

    // 3 fp16 hops, then hop4 fused with GEMM1+SELU+GEMM2
    k_spmm_h<<<nb8, tb>>>(H1, H2, N);
    k_spmm_h<<<nb8, tb>>>(H2, H1, N);
    k_spmm_h<<<nb8, tb>>>(H1, H2, N);
    k_hop4_fused<<<nbF, tb>>>(H2, buf16, W1, b1, W2, b2, N);

    // conv2: 16-wide hop + log_softmax
    k_hop16<<<nbQ, tb>>>(buf16, out, N);
}

// round 12
// speedup vs baseline: 1.0815x; 1.0815x over previous
#include <cuda_runtime.h>
#include <cuda_fp16.h>
#include <math.h>

#define NMAX 100000
#define EMAX 1000000
#define F    64
#define FO   16
// padded CSR: each row rounded up to multiple of 8 with (col=0, w=0) dummies
#define EPADMAX (EMAX + 8 * NMAX)

// ---------------- scratch (no allocations allowed) ----------------
__device__ int    g_hist[NMAX];
__device__ int    g_rank[EMAX];
__device__ int    g_rowptr[NMAX + 1];
__device__ int2   g_colw[EPADMAX];       // packed (col, w-bits), padded rows
__device__ float  g_dinv[NMAX];
__device__ __half g_bufH1[(size_t)NMAX * F];
__device__ __half g_bufH2[(size_t)NMAX * F];
__device__ float  g_buf16[(size_t)NMAX * FO];
__device__ int    g_part[1024];

// ---------------- x (fp32) -> fp16, plus zeroing of hist ---------------------
__global__ void k_cvt(const float* __restrict__ x, __half* __restrict__ dst,
                      int total4, int nNodes) {
    int i = blockIdx.x * blockDim.x + threadIdx.x;
    if (i < nNodes) g_hist[i] = 0;
    if (i >= total4) return;
    float4 v = ((const float4*)x)[i];
    __half2 lo = __floats2half2_rn(v.x, v.y);
    __half2 hi = __floats2half2_rn(v.z, v.w);
    uint2 u;
    u.x = *(unsigned*)&lo; u.y = *(unsigned*)&hi;
    ((uint2*)dst)[i] = u;
}

// ---------------- CSR build ----------------
// histogram + per-edge rank in one atomic pass
__global__ void k_hist_rank(const int* __restrict__ ei, int E) {
    int e = blockIdx.x * blockDim.x + threadIdx.x;
    if (e < E) g_rank[e] = atomicAdd(&g_hist[ei[e]], 1);
}

// block-local exclusive scan of PADDED degrees (1024 threads) + dinv
__global__ void k_scan_block(int n) {
    __shared__ int sh[1024];
    int gid = blockIdx.x * 1024 + threadIdx.x;
    int v  = (gid < n) ? g_hist[gid] : 0;
    int vp = (v + 7) & ~7;               // pad to multiple of 8
    if (gid < n) g_dinv[gid] = rsqrtf((float)v + 1.0f);   // +1 self loop
    sh[threadIdx.x] = vp;
    __syncthreads();
    #pragma unroll
    for (int off = 1; off < 1024; off <<= 1) {
        int t = (threadIdx.x >= off) ? sh[threadIdx.x - off] : 0;
        __syncthreads();
        sh[threadIdx.x] += t;
        __syncthreads();
    }
    if (gid < n) g_rowptr[gid] = sh[threadIdx.x] - vp;    // exclusive (padded)
    if (threadIdx.x == 1023) g_part[blockIdx.x] = sh[1023];
}

// add sum of partials below this block; block 0 also writes rowptr[n] = total
__global__ void k_scan_add(int n) {
    __shared__ int sred[1024];
    if (blockIdx.x == 0 && threadIdx.x == 0) {
        int tot = 0;
        for (int b = 0; b < (int)gridDim.x; b++) tot += g_part[b];
        g_rowptr[n] = tot;
    }
    int v = (threadIdx.x < blockIdx.x) ? g_part[threadIdx.x] : 0;
    sred[threadIdx.x] = v;
    __syncthreads();
    #pragma unroll
    for (int off = 512; off >= 1; off >>= 1) {
        if (threadIdx.x < off) sred[threadIdx.x] += sred[threadIdx.x + off];
        __syncthreads();
    }
    int base = sred[0];
    int gid = blockIdx.x * 1024 + threadIdx.x;
    if (gid < n) g_rowptr[gid] += base;
}

// atomic-free fill (rank-based) + dummy padding (first n threads pad their row)
__global__ void k_fill(const int* __restrict__ ei, int E, int n) {
    int e = blockIdx.x * blockDim.x + threadIdx.x;
    if (e < n) {
        int deg = g_hist[e];
        int st = g_rowptr[e] + deg;
        int en = g_rowptr[e] + ((deg + 7) & ~7);
        for (int p = st; p < en; p++)
            g_colw[p] = make_int2(0, 0);   // col 0, weight 0.0f: hot, exact no-op
    }
    if (e >= E) return;
    int r = ei[e];
    int c = ei[E + e];
    int pos = g_rowptr[r] + g_rank[e];
    float w = g_dinv[r] * g_dinv[c];
    g_colw[pos] = make_int2(c, __float_as_int(w));
}

// ---------------- fp16 SpMM core: 8 lanes/node, 8 features per lane ----------
// padded rows: single uniform unroll-8 loop, no tail
__device__ __forceinline__ void h8_acc(uint4 u, float w, float* acc) {
    __half2* h = (__half2*)&u;
    float2 f0 = __half22float2(h[0]);
    float2 f1 = __half22float2(h[1]);
    float2 f2 = __half22float2(h[2]);
    float2 f3 = __half22float2(h[3]);
    acc[0] += w * f0.x; acc[1] += w * f0.y;
    acc[2] += w * f1.x; acc[3] += w * f1.y;
    acc[4] += w * f2.x; acc[5] += w * f2.y;
    acc[6] += w * f3.x; acc[7] += w * f3.y;
}

__device__ __forceinline__ void spmm_row_h(const __half* __restrict__ src, int node,
                                           int l8, float* acc) {
    float d  = g_dinv[node];
    float sw = d * d;
    #pragma unroll
    for (int i = 0; i < 8; i++) acc[i] = 0.f;
    h8_acc(((const uint4*)(src + (size_t)node * F))[l8], sw, acc);
    int s = g_rowptr[node], e = g_rowptr[node + 1];
    for (int p = s; p < e; p += 8) {
        int jj[8]; float ww[8];
        #pragma unroll
        for (int q = 0; q < 8; q++) {
            int2 cw = g_colw[p + q];
            jj[q] = cw.x; ww[q] = __int_as_float(cw.y);
        }
        uint4 vv[8];
        #pragma unroll
        for (int q = 0; q < 8; q++)
            vv[q] = ((const uint4*)(src + (size_t)jj[q] * F))[l8];
        #pragma unroll
        for (int q = 0; q < 8; q++)
            h8_acc(vv[q], ww[q], acc);
    }
}

__device__ __forceinline__ uint4 f8_to_h8(const float* acc) {
    __half2 h0 = __floats2half2_rn(acc[0], acc[1]);
    __half2 h1 = __floats2half2_rn(acc[2], acc[3]);
    __half2 h2 = __floats2half2_rn(acc[4], acc[5]);
    __half2 h3 = __floats2half2_rn(acc[6], acc[7]);
    uint4 u;
    u.x = *(unsigned*)&h0; u.y = *(unsigned*)&h1;
    u.z = *(unsigned*)&h2; u.w = *(unsigned*)&h3;
    return u;
}

__global__ void k_spmm_h(const __half* __restrict__ src, __half* __restrict__ dst, int n) {
    int tid  = blockIdx.x * blockDim.x + threadIdx.x;
    int node = tid >> 3;
    int l8   = tid & 7;
    if (node >= n) return;
    float acc[8];
    spmm_row_h(src, node, l8, acc);
    ((uint4*)(dst + (size_t)node * F))[l8] = f8_to_h8(acc);
}

// ---------------- hop4 fused: fp16 SpMM + W1 + SELU + W2 -> N x 16 -----------
#define PAD 4
__global__ void k_hop4_fused(const __half* __restrict__ src, float* __restrict__ dst16,
                             const float* __restrict__ W1, const float* __restrict__ b1,
                             const float* __restrict__ W2, const float* __restrict__ b2, int n) {
    __shared__ float W1s[F * F];
    __shared__ float W2s[F * FO];
    __shared__ float b2s[FO];
    __shared__ float y_s[32][F + PAD];
    __shared__ float h_s[32][F + PAD];
    for (int t = threadIdx.x; t < F * F; t += blockDim.x) W1s[t] = W1[t];
    for (int t = threadIdx.x; t < F * FO; t += blockDim.x) W2s[t] = W2[t];
    if (threadIdx.x < FO) b2s[threadIdx.x] = b2[threadIdx.x];
    __syncthreads();

    int nodeL = threadIdx.x >> 3;
    int l8    = threadIdx.x & 7;
    int node  = blockIdx.x * 32 + nodeL;

    float acc[8];
    #pragma unroll
    for (int i = 0; i < 8; i++) acc[i] = 0.f;
    if (node < n) spmm_row_h(src, node, l8, acc);
    ((float4*)&y_s[nodeL][8 * l8])[0]     = make_float4(acc[0], acc[1], acc[2], acc[3]);
    ((float4*)&y_s[nodeL][8 * l8 + 4])[0] = make_float4(acc[4], acc[5], acc[6], acc[7]);
    __syncwarp();

    // GEMM1 + SELU: lane l8 computes features l8 + 8*m, m=0..7
    float h[8];
    #pragma unroll
    for (int m = 0; m < 8; m++) h[m] = b1[l8 + 8 * m];
    #pragma unroll 8
    for (int k = 0; k < F; k++) {
        float yk = y_s[nodeL][k];
        #pragma unroll
        for (int m = 0; m < 8; m++)
            h[m] += yk * W1s[k * F + l8 + 8 * m];
    }
    const float al = 1.6732632423543772f, sc = 1.0507009873554805f;
    #pragma unroll
    for (int m = 0; m < 8; m++) {
        h[m] = (h[m] > 0.f) ? sc * h[m] : sc * al * expm1f(h[m]);
        h_s[nodeL][l8 + 8 * m] = h[m];
    }
    __syncwarp();

    // GEMM2: lane l8 computes output features l8 and l8+8
    float z0 = b2s[l8], z1 = b2s[l8 + 8];
    #pragma unroll 8
    for (int k = 0; k < F; k++) {
        float hk = h_s[nodeL][k];
        z0 += hk * W2s[k * FO + l8];
        z1 += hk * W2s[k * FO + l8 + 8];
    }
    if (node < n) {
        dst16[(size_t)node * FO + l8]     = z0;
        dst16[(size_t)node * FO + l8 + 8] = z1;
    }
}

// ---------------- final 16-wide hop + log_softmax: 4 lanes/node, float4 -------
// padded rows are multiples of 8 (hence of 4): uniform 4-batch loop, no tail
__global__ void k_hop16(const float* __restrict__ src16, float* __restrict__ out, int n) {
    int tid  = blockIdx.x * blockDim.x + threadIdx.x;
    int node = tid >> 2;
    int l4   = tid & 3;
    if (node >= n) return;
    float d = g_dinv[node];
    float sw = d * d;
    float4 a = ((const float4*)(src16 + (size_t)node * FO))[l4];
    float4 acc = make_float4(sw * a.x, sw * a.y, sw * a.z, sw * a.w);
    int s = g_rowptr[node], e = g_rowptr[node + 1];
    for (int p = s; p < e; p += 4) {
        int jj[4]; float ww[4];
        #pragma unroll
        for (int q = 0; q < 4; q++) {
            int2 cw = g_colw[p + q];
            jj[q] = cw.x; ww[q] = __int_as_float(cw.y);
        }
        float4 v0 = ((const float4*)(src16 + (size_t)jj[0] * FO))[l4];
        float4 v1 = ((const float4*)(src16 + (size_t)jj[1] * FO))[l4];
        float4 v2 = ((const float4*)(src16 + (size_t)jj[2] * FO))[l4];
        float4 v3 = ((const float4*)(src16 + (size_t)jj[3] * FO))[l4];
        acc.x += ww[0] * v0.x + ww[1] * v1.x + ww[2] * v2.x + ww[3] * v3.x;
        acc.y += ww[0] * v0.y + ww[1] * v1.y + ww[2] * v2.y + ww[3] * v3.y;
        acc.z += ww[0] * v0.z + ww[1] * v1.z + ww[2] * v2.z + ww[3] * v3.z;
        acc.w += ww[0] * v0.w + ww[1] * v1.w + ww[2] * v2.w + ww[3] * v3.w;
    }

    float m = fmaxf(fmaxf(acc.x, acc.y), fmaxf(acc.z, acc.w));
    m = fmaxf(m, __shfl_xor_sync(0xffffffffu, m, 1, 4));
    m = fmaxf(m, __shfl_xor_sync(0xffffffffu, m, 2, 4));
    float ssum = expf(acc.x - m) + expf(acc.y - m) + expf(acc.z - m) + expf(acc.w - m);
    ssum += __shfl_xor_sync(0xffffffffu, ssum, 1, 4);
    ssum += __shfl_xor_sync(0xffffffffu, ssum, 2, 4);
    float lse = m + logf(ssum);
    float4 r = make_float4(acc.x - lse, acc.y - lse, acc.z - lse, acc.w - lse);
    ((float4*)(out + (size_t)node * FO))[l4] = r;
}

// ---------------- launch ----------------
extern "C" void kernel_launch(void* const* d_in, const int* in_sizes, int n_in,
                              void* d_out, int out_size) {
    const float* x  = (const float*)d_in[0];
    const float* W1 = (const float*)d_in[1];
    const float* b1 = (const float*)d_in[2];
    const float* W2 = (const float*)d_in[3];
    const float* b2 = (const float*)d_in[4];
    const int*   ei = (const int*)  d_in[5];
    int N = in_sizes[0] / F;
    int E = in_sizes[5] / 2;
    float* out = (float*)d_out;

    __half *H1, *H2;
    float  *buf16;
    cudaGetSymbolAddress((void**)&H1, g_bufH1);
    cudaGetSymbolAddress((void**)&H2, g_bufH2);
    cudaGetSymbolAddress((void**)&buf16, g_buf16);

    int tb = 256;
    int nbE    = (E + tb - 1) / tb;
    int nb1024 = (N + 1023) / 1024;
    int nbC    = (N * F / 4 + tb - 1) / tb;    // convert: float4 per thread (covers hist zeroing)
    int nb8    = (N * 8 + tb - 1) / tb;        // 8 lanes/node
    int nbF    = (N + 31) / 32;                // hop4 fused: 32 nodes/block
    int nbQ    = (N * 4 + tb - 1) / tb;        // 4 lanes/node

    // cvt first: also zeroes g_hist
    k_cvt       <<<nbC, tb>>>(x, H1, N * F / 4, N);
    // padded CSR build (rank-based fill + hot dummy padding)
    k_hist_rank <<<nbE, tb>>>(ei, E);
    k_scan_block<<<nb1024, 1024>>>(N);
    k_scan_add  <<<nb1024, 1024>>>(N);
    k_fill      <<<nbE, tb>>>(ei, E, N);

    // 3 fp16 hops, then hop4 fused with GEMM1+SELU+GEMM2
    k_spmm_h<<<nb8, tb>>>(H1, H2, N);
    k_spmm_h<<<nb8, tb>>>(H2, H1, N);
    k_spmm_h<<<nb8, tb>>>(H1, H2, N);
    k_hop4_fused<<<nbF, tb>>>(H2, buf16, W1, b1, W2, b2, N);

    // conv2: 16-wide hop + log_softmax
    k_hop16<<<nbQ, tb>>>(buf16, out, N);
}

// round 13
// speedup vs baseline: 1.0926x; 1.0103x over previous
#include <cuda_runtime.h>
#include <cuda_fp16.h>
#include <math.h>

#define NMAX 100000
#define EMAX 1000000
#define F    64
#define FO   16
// padded CSR: each row rounded up to multiple of 8 with (col=0, w=0) dummies
#define EPADMAX (EMAX + 8 * NMAX)

// ---------------- scratch (no allocations allowed) ----------------
// g_hist is zero on load (BSS) and re-zeroed at the end of every k_fill,
// so each kernel_launch (and each graph replay) sees hist == 0 on entry.
__device__ int    g_hist[NMAX];
__device__ int    g_rank[EMAX];
__device__ int    g_rowptr[NMAX + 1];
__device__ int2   g_colw[EPADMAX];       // packed (col, w-bits), padded rows
__device__ float  g_dinv[NMAX];
__device__ __half g_bufH1[(size_t)NMAX * F];
__device__ __half g_bufH2[(size_t)NMAX * F];
__device__ float  g_buf16[(size_t)NMAX * FO];
__device__ int    g_part[1024];

// ---------------- fused: x fp32->fp16 convert + edge histogram/rank ----------
// grid covers max(total4, E) threads; the two jobs use disjoint predicates.
__global__ void k_cvt_hist(const float* __restrict__ x, __half* __restrict__ dst,
                           int total4, const int* __restrict__ ei, int E) {
    int i = blockIdx.x * blockDim.x + threadIdx.x;
    if (i < E) g_rank[i] = atomicAdd(&g_hist[ei[i]], 1);
    if (i >= total4) return;
    float4 v = ((const float4*)x)[i];
    __half2 lo = __floats2half2_rn(v.x, v.y);
    __half2 hi = __floats2half2_rn(v.z, v.w);
    uint2 u;
    u.x = *(unsigned*)&lo; u.y = *(unsigned*)&hi;
    ((uint2*)dst)[i] = u;
}

// ---------------- CSR build ----------------
// block-local exclusive scan of PADDED degrees (1024 threads) + dinv
__global__ void k_scan_block(int n) {
    __shared__ int sh[1024];
    int gid = blockIdx.x * 1024 + threadIdx.x;
    int v  = (gid < n) ? g_hist[gid] : 0;
    int vp = (v + 7) & ~7;               // pad to multiple of 8
    if (gid < n) g_dinv[gid] = rsqrtf((float)v + 1.0f);   // +1 self loop
    sh[threadIdx.x] = vp;
    __syncthreads();
    #pragma unroll
    for (int off = 1; off < 1024; off <<= 1) {
        int t = (threadIdx.x >= off) ? sh[threadIdx.x - off] : 0;
        __syncthreads();
        sh[threadIdx.x] += t;
        __syncthreads();
    }
    if (gid < n) g_rowptr[gid] = sh[threadIdx.x] - vp;    // exclusive (padded)
    if (threadIdx.x == 1023) g_part[blockIdx.x] = sh[1023];
}

// add sum of partials below this block; block 0 also writes rowptr[n] = total
__global__ void k_scan_add(int n) {
    __shared__ int sred[1024];
    if (blockIdx.x == 0 && threadIdx.x == 0) {
        int tot = 0;
        for (int b = 0; b < (int)gridDim.x; b++) tot += g_part[b];
        g_rowptr[n] = tot;
    }
    int v = (threadIdx.x < blockIdx.x) ? g_part[threadIdx.x] : 0;
    sred[threadIdx.x] = v;
    __syncthreads();
    #pragma unroll
    for (int off = 512; off >= 1; off >>= 1) {
        if (threadIdx.x < off) sred[threadIdx.x] += sred[threadIdx.x + off];
        __syncthreads();
    }
    int base = sred[0];
    int gid = blockIdx.x * 1024 + threadIdx.x;
    if (gid < n) g_rowptr[gid] += base;
}

// atomic-free fill (rank-based) + dummy padding; re-zero g_hist for next replay
__global__ void k_fill(const int* __restrict__ ei, int E, int n) {
    int e = blockIdx.x * blockDim.x + threadIdx.x;
    if (e < n) {
        int deg = g_hist[e];
        int st = g_rowptr[e] + deg;
        int en = g_rowptr[e] + ((deg + 7) & ~7);
        for (int p = st; p < en; p++)
            g_colw[p] = make_int2(0, 0);   // col 0, weight 0.0f: hot, exact no-op
        g_hist[e] = 0;                     // restore invariant for next launch
    }
    if (e >= E) return;
    int r = ei[e];
    int c = ei[E + e];
    int pos = g_rowptr[r] + g_rank[e];
    float w = g_dinv[r] * g_dinv[c];
    g_colw[pos] = make_int2(c, __float_as_int(w));
}

// ---------------- fp16 SpMM core: 8 lanes/node, 8 features per lane ----------
// padded rows: single uniform unroll-8 loop, no tail
__device__ __forceinline__ void h8_acc(uint4 u, float w, float* acc) {
    __half2* h = (__half2*)&u;
    float2 f0 = __half22float2(h[0]);
    float2 f1 = __half22float2(h[1]);
    float2 f2 = __half22float2(h[2]);
    float2 f3 = __half22float2(h[3]);
    acc[0] += w * f0.x; acc[1] += w * f0.y;
    acc[2] += w * f1.x; acc[3] += w * f1.y;
    acc[4] += w * f2.x; acc[5] += w * f2.y;
    acc[6] += w * f3.x; acc[7] += w * f3.y;
}

__device__ __forceinline__ void spmm_row_h(const __half* __restrict__ src, int node,
                                           int l8, float* acc) {
    float d  = g_dinv[node];
    float sw = d * d;
    #pragma unroll
    for (int i = 0; i < 8; i++) acc[i] = 0.f;
    h8_acc(((const uint4*)(src + (size_t)node * F))[l8], sw, acc);
    int s = g_rowptr[node], e = g_rowptr[node + 1];
    for (int p = s; p < e; p += 8) {
        int jj[8]; float ww[8];
        #pragma unroll
        for (int q = 0; q < 8; q++) {
            int2 cw = g_colw[p + q];
            jj[q] = cw.x; ww[q] = __int_as_float(cw.y);
        }
        uint4 vv[8];
        #pragma unroll
        for (int q = 0; q < 8; q++)
            vv[q] = ((const uint4*)(src + (size_t)jj[q] * F))[l8];
        #pragma unroll
        for (int q = 0; q < 8; q++)
            h8_acc(vv[q], ww[q], acc);
    }
}

__device__ __forceinline__ uint4 f8_to_h8(const float* acc) {
    __half2 h0 = __floats2half2_rn(acc[0], acc[1]);
    __half2 h1 = __floats2half2_rn(acc[2], acc[3]);
    __half2 h2 = __floats2half2_rn(acc[4], acc[5]);
    __half2 h3 = __floats2half2_rn(acc[6], acc[7]);
    uint4 u;
    u.x = *(unsigned*)&h0; u.y = *(unsigned*)&h1;
    u.z = *(unsigned*)&h2; u.w = *(unsigned*)&h3;
    return u;
}

__global__ void k_spmm_h(const __half* __restrict__ src, __half* __restrict__ dst, int n) {
    int tid  = blockIdx.x * blockDim.x + threadIdx.x;
    int node = tid >> 3;
    int l8   = tid & 7;
    if (node >= n) return;
    float acc[8];
    spmm_row_h(src, node, l8, acc);
    ((uint4*)(dst + (size_t)node * F))[l8] = f8_to_h8(acc);
}

// ---------------- hop4 fused: fp16 SpMM + W1 + SELU + W2 -> N x 16 -----------
#define PAD 4
__global__ void k_hop4_fused(const __half* __restrict__ src, float* __restrict__ dst16,
                             const float* __restrict__ W1, const float* __restrict__ b1,
                             const float* __restrict__ W2, const float* __restrict__ b2, int n) {
    __shared__ float W1s[F * F];
    __shared__ float W2s[F * FO];
    __shared__ float b2s[FO];
    __shared__ float y_s[32][F + PAD];
    __shared__ float h_s[32][F + PAD];
    for (int t = threadIdx.x; t < F * F; t += blockDim.x) W1s[t] = W1[t];
    for (int t = threadIdx.x; t < F * FO; t += blockDim.x) W2s[t] = W2[t];
    if (threadIdx.x < FO) b2s[threadIdx.x] = b2[threadIdx.x];
    __syncthreads();

    int nodeL = threadIdx.x >> 3;
    int l8    = threadIdx.x & 7;
    int node  = blockIdx.x * 32 + nodeL;

    float acc[8];
    #pragma unroll
    for (int i = 0; i < 8; i++) acc[i] = 0.f;
    if (node < n) spmm_row_h(src, node, l8, acc);
    ((float4*)&y_s[nodeL][8 * l8])[0]     = make_float4(acc[0], acc[1], acc[2], acc[3]);
    ((float4*)&y_s[nodeL][8 * l8 + 4])[0] = make_float4(acc[4], acc[5], acc[6], acc[7]);
    __syncwarp();

    // GEMM1 + SELU: lane l8 computes features l8 + 8*m, m=0..7
    float h[8];
    #pragma unroll
    for (int m = 0; m < 8; m++) h[m] = b1[l8 + 8 * m];
    #pragma unroll 8
    for (int k = 0; k < F; k++) {
        float yk = y_s[nodeL][k];
        #pragma unroll
        for (int m = 0; m < 8; m++)
            h[m] += yk * W1s[k * F + l8 + 8 * m];
    }
    const float al = 1.6732632423543772f, sc = 1.0507009873554805f;
    #pragma unroll
    for (int m = 0; m < 8; m++) {
        h[m] = (h[m] > 0.f) ? sc * h[m] : sc * al * expm1f(h[m]);
        h_s[nodeL][l8 + 8 * m] = h[m];
    }
    __syncwarp();

    // GEMM2: lane l8 computes output features l8 and l8+8
    float z0 = b2s[l8], z1 = b2s[l8 + 8];
    #pragma unroll 8
    for (int k = 0; k < F; k++) {
        float hk = h_s[nodeL][k];
        z0 += hk * W2s[k * FO + l8];
        z1 += hk * W2s[k * FO + l8 + 8];
    }
    if (node < n) {
        dst16[(size_t)node * FO + l8]     = z0;
        dst16[(size_t)node * FO + l8 + 8] = z1;
    }
}

// ---------------- final 16-wide hop + log_softmax: 4 lanes/node, float4 -------
// padded rows are multiples of 8 (hence of 4): uniform 4-batch loop, no tail
__global__ void k_hop16(const float* __restrict__ src16, float* __restrict__ out, int n) {
    int tid  = blockIdx.x * blockDim.x + threadIdx.x;
    int node = tid >> 2;
    int l4   = tid & 3;
    if (node >= n) return;
    float d = g_dinv[node];
    float sw = d * d;
    float4 a = ((const float4*)(src16 + (size_t)node * FO))[l4];
    float4 acc = make_float4(sw * a.x, sw * a.y, sw * a.z, sw * a.w);
    int s = g_rowptr[node], e = g_rowptr[node + 1];
    for (int p = s; p < e; p += 4) {
        int jj[4]; float ww[4];
        #pragma unroll
        for (int q = 0; q < 4; q++) {
            int2 cw = g_colw[p + q];
            jj[q] = cw.x; ww[q] = __int_as_float(cw.y);
        }
        float4 v0 = ((const float4*)(src16 + (size_t)jj[0] * FO))[l4];
        float4 v1 = ((const float4*)(src16 + (size_t)jj[1] * FO))[l4];
        float4 v2 = ((const float4*)(src16 + (size_t)jj[2] * FO))[l4];
        float4 v3 = ((const float4*)(src16 + (size_t)jj[3] * FO))[l4];
        acc.x += ww[0] * v0.x + ww[1] * v1.x + ww[2] * v2.x + ww[3] * v3.x;
        acc.y += ww[0] * v0.y + ww[1] * v1.y + ww[2] * v2.y + ww[3] * v3.y;
        acc.z += ww[0] * v0.z + ww[1] * v1.z + ww[2] * v2.z + ww[3] * v3.z;
        acc.w += ww[0] * v0.w + ww[1] * v1.w + ww[2] * v2.w + ww[3] * v3.w;
    }

    float m = fmaxf(fmaxf(acc.x, acc.y), fmaxf(acc.z, acc.w));
    m = fmaxf(m, __shfl_xor_sync(0xffffffffu, m, 1, 4));
    m = fmaxf(m, __shfl_xor_sync(0xffffffffu, m, 2, 4));
    float ssum = expf(acc.x - m) + expf(acc.y - m) + expf(acc.z - m) + expf(acc.w - m);
    ssum += __shfl_xor_sync(0xffffffffu, ssum, 1, 4);
    ssum += __shfl_xor_sync(0xffffffffu, ssum, 2, 4);
    float lse = m + logf(ssum);
    float4 r = make_float4(acc.x - lse, acc.y - lse, acc.z - lse, acc.w - lse);
    ((float4*)(out + (size_t)node * FO))[l4] = r;
}

// ---------------- launch ----------------
extern "C" void kernel_launch(void* const* d_in, const int* in_sizes, int n_in,
                              void* d_out, int out_size) {
    const float* x  = (const float*)d_in[0];
    const float* W1 = (const float*)d_in[1];
    const float* b1 = (const float*)d_in[2];
    const float* W2 = (const float*)d_in[3];
    const float* b2 = (const float*)d_in[4];
    const int*   ei = (const int*)  d_in[5];
    int N = in_sizes[0] / F;
    int E = in_sizes[5] / 2;
    float* out = (float*)d_out;

    __half *H1, *H2;
    float  *buf16;
    cudaGetSymbolAddress((void**)&H1, g_bufH1);
    cudaGetSymbolAddress((void**)&H2, g_bufH2);
    cudaGetSymbolAddress((void**)&buf16, g_buf16);

    int tb = 256;
    int total4 = N * F / 4;
    int nbCH   = ((total4 > E ? total4 : E) + tb - 1) / tb;  // fused cvt+hist grid
    int nbE    = (E + tb - 1) / tb;
    int nb1024 = (N + 1023) / 1024;
    int nb8    = (N * 8 + tb - 1) / tb;        // 8 lanes/node
    int nbF    = (N + 31) / 32;                // hop4 fused: 32 nodes/block
    int nbQ    = (N * 4 + tb - 1) / tb;        // 4 lanes/node

    // fused convert + histogram/rank (hist is 0 on entry by invariant)
    k_cvt_hist  <<<nbCH, tb>>>(x, H1, total4, ei, E);
    // padded CSR build (rank-based fill + hot dummy padding; re-zeros hist)
    k_scan_block<<<nb1024, 1024>>>(N);
    k_scan_add  <<<nb1024, 1024>>>(N);
    k_fill      <<<nbE, tb>>>(ei, E, N);

    // 3 fp16 hops, then hop4 fused with GEMM1+SELU+GEMM2
    k_spmm_h<<<nb8, tb>>>(H1, H2, N);
    k_spmm_h<<<nb8, tb>>>(H2, H1, N);
    k_spmm_h<<<nb8, tb>>>(H1, H2, N);
    k_hop4_fused<<<nbF, tb>>>(H2, buf16, W1, b1, W2, b2, N);

    // conv2: 16-wide hop + log_softmax
    k_hop16<<<nbQ, tb>>>(buf16, out, N);
}

// round 16
// speedup vs baseline: 1.1887x; 1.0879x over previous
#include <cuda_runtime.h>
#include <cuda_fp16.h>
#include <math.h>

#define NMAX 100000
#define EMAX 1000000
#define F    64
#define FO   16
// padded CSR: each row rounded up to multiple of 8 with dummy cols -> zero row N
#define EPADMAX (EMAX + 8 * NMAX)

// ---------------- scratch (no allocations allowed) ----------------
// g_hist is zero on load (BSS) and re-zeroed at the end of every k_fill.
__device__ int    g_hist[NMAX];
__device__ int    g_rank[EMAX];
__device__ int    g_rowptr[NMAX + 1];
__device__ int    g_col[EPADMAX];                    // col only; no weights
__device__ float  g_dinv[NMAX];
__device__ __half g_bufH1[(size_t)(NMAX + 1) * F];   // +1: zero dummy row
__device__ __half g_bufH2[(size_t)(NMAX + 1) * F];
__device__ float  g_buf16[(size_t)(NMAX + 1) * FO];
__device__ int    g_part[1024];

// ---------------- fused: x fp32->fp16 convert + edge histogram/rank ----------
// also zeroes the dummy row N of all three feature buffers
__global__ void k_cvt_hist(const float* __restrict__ x, int total4,
                           const int* __restrict__ ei, int E, int n) {
    int i = blockIdx.x * blockDim.x + threadIdx.x;
    if (i < E) g_rank[i] = atomicAdd(&g_hist[ei[i]], 1);
    if (i < 16) {
        ((uint2*)(g_bufH1 + (size_t)n * F))[i] = make_uint2(0, 0);
        ((uint2*)(g_bufH2 + (size_t)n * F))[i] = make_uint2(0, 0);
        if (i < 4) ((float4*)(g_buf16 + (size_t)n * FO))[i] = make_float4(0.f, 0.f, 0.f, 0.f);
    }
    if (i >= total4) return;
    float4 v = ((const float4*)x)[i];
    __half2 lo = __floats2half2_rn(v.x, v.y);
    __half2 hi = __floats2half2_rn(v.z, v.w);
    uint2 u;
    u.x = *(unsigned*)&lo; u.y = *(unsigned*)&hi;
    ((uint2*)g_bufH1)[i] = u;
}

// ---------------- CSR build ----------------
// block-local exclusive scan of PADDED degrees (1024 threads) + dinv
__global__ void k_scan_block(int n) {
    __shared__ int sh[1024];
    int gid = blockIdx.x * 1024 + threadIdx.x;
    int v  = (gid < n) ? g_hist[gid] : 0;
    int vp = (v + 7) & ~7;               // pad to multiple of 8
    if (gid < n) g_dinv[gid] = rsqrtf((float)v + 1.0f);   // +1 self loop
    sh[threadIdx.x] = vp;
    __syncthreads();
    #pragma unroll
    for (int off = 1; off < 1024; off <<= 1) {
        int t = (threadIdx.x >= off) ? sh[threadIdx.x - off] : 0;
        __syncthreads();
        sh[threadIdx.x] += t;
        __syncthreads();
    }
    if (gid < n) g_rowptr[gid] = sh[threadIdx.x] - vp;    // exclusive (padded)
    if (threadIdx.x == 1023) g_part[blockIdx.x] = sh[1023];
}

__global__ void k_scan_add(int n) {
    __shared__ int sred[1024];
    if (blockIdx.x == 0 && threadIdx.x == 0) {
        int tot = 0;
        for (int b = 0; b < (int)gridDim.x; b++) tot += g_part[b];
        g_rowptr[n] = tot;
    }
    int v = (threadIdx.x < blockIdx.x) ? g_part[threadIdx.x] : 0;
    sred[threadIdx.x] = v;
    __syncthreads();
    #pragma unroll
    for (int off = 512; off >= 1; off >>= 1) {
        if (threadIdx.x < off) sred[threadIdx.x] += sred[threadIdx.x + off];
        __syncthreads();
    }
    int base = sred[0];
    int gid = blockIdx.x * 1024 + threadIdx.x;
    if (gid < n) g_rowptr[gid] += base;
}

// fill (atomic-free, col only) + dummy padding + u = dinv*x scaling + hist re-zero
__global__ void k_fill(const int* __restrict__ ei, int E, int n) {
    int e = blockIdx.x * blockDim.x + threadIdx.x;
    if (e < n * 8) {                      // scale H1 in place: u = dinv * x
        int node = e >> 3;
        float dv = g_dinv[node];
        uint4 u = ((uint4*)g_bufH1)[e];
        __half2* h = (__half2*)&u;
        #pragma unroll
        for (int k = 0; k < 4; k++) {
            float2 f = __half22float2(h[k]);
            h[k] = __floats2half2_rn(f.x * dv, f.y * dv);
        }
        ((uint4*)g_bufH1)[e] = u;
    }
    if (e < n) {                          // dummy padding -> zero row n
        int deg = g_hist[e];
        int st = g_rowptr[e] + deg;
        int en = g_rowptr[e] + ((deg + 7) & ~7);
        for (int p = st; p < en; p++) g_col[p] = n;
        g_hist[e] = 0;                    // restore invariant for next launch
    }
    if (e >= E) return;
    int r = ei[e];
    int c = ei[E + e];
    g_col[g_rowptr[r] + g_rank[e]] = c;
}

// ---------------- fp16 gather-sum core: 8 lanes/node, 8 features per lane ----
__device__ __forceinline__ void h8_add(uint4 u, float* acc) {
    __half2* h = (__half2*)&u;
    float2 f0 = __half22float2(h[0]);
    float2 f1 = __half22float2(h[1]);
    float2 f2 = __half22float2(h[2]);
    float2 f3 = __half22float2(h[3]);
    acc[0] += f0.x; acc[1] += f0.y;
    acc[2] += f1.x; acc[3] += f1.y;
    acc[4] += f2.x; acc[5] += f2.y;
    acc[6] += f3.x; acc[7] += f3.y;
}

// acc = u_self + sum(u_neighbors); caller applies the dinv power
__device__ __forceinline__ void gather_row_h(const __half* __restrict__ src, int node,
                                             int l8, float* acc) {
    #pragma unroll
    for (int i = 0; i < 8; i++) acc[i] = 0.f;
    h8_add(((const uint4*)(src + (size_t)node * F))[l8], acc);
    int s = g_rowptr[node], e = g_rowptr[node + 1];
    for (int p = s; p < e; p += 8) {      // s,e multiples of 8; int4-aligned
        int4 c0 = *(const int4*)(g_col + p);
        int4 c1 = *(const int4*)(g_col + p + 4);
        uint4 v0 = ((const uint4*)(src + (size_t)c0.x * F))[l8];
        uint4 v1 = ((const uint4*)(src + (size_t)c0.y * F))[l8];
        uint4 v2 = ((const uint4*)(src + (size_t)c0.z * F))[l8];
        uint4 v3 = ((const uint4*)(src + (size_t)c0.w * F))[l8];
        uint4 v4 = ((const uint4*)(src + (size_t)c1.x * F))[l8];
        uint4 v5 = ((const uint4*)(src + (size_t)c1.y * F))[l8];
        uint4 v6 = ((const uint4*)(src + (size_t)c1.z * F))[l8];
        uint4 v7 = ((const uint4*)(src + (size_t)c1.w * F))[l8];
        h8_add(v0, acc); h8_add(v1, acc); h8_add(v2, acc); h8_add(v3, acc);
        h8_add(v4, acc); h8_add(v5, acc); h8_add(v6, acc); h8_add(v7, acc);
    }
}

__device__ __forceinline__ uint4 f8_to_h8(const float* acc) {
    __half2 h0 = __floats2half2_rn(acc[0], acc[1]);
    __half2 h1 = __floats2half2_rn(acc[2], acc[3]);
    __half2 h2 = __floats2half2_rn(acc[4], acc[5]);
    __half2 h3 = __floats2half2_rn(acc[6], acc[7]);
    uint4 u;
    u.x = *(unsigned*)&h0; u.y = *(unsigned*)&h1;
    u.z = *(unsigned*)&h2; u.w = *(unsigned*)&h3;
    return u;
}

// hops 1-3: u' = dinv^2 * (u_i + sum u_j)
__global__ void k_spmm_h(const __half* __restrict__ src, __half* __restrict__ dst, int n) {
    int tid  = blockIdx.x * blockDim.x + threadIdx.x;
    int node = tid >> 3;
    int l8   = tid & 7;
    if (node >= n) return;
    float acc[8];
    gather_row_h(src, node, l8, acc);
    float d = g_dinv[node];
    float sw = d * d;
    #pragma unroll
    for (int i = 0; i < 8; i++) acc[i] *= sw;
    ((uint4*)(dst + (size_t)node * F))[l8] = f8_to_h8(acc);
}

// ---------------- hop4 fused: gather + W1 + SELU + W2 -> z~ = dinv*z ---------
#define PAD 4
__global__ void k_hop4_fused(const __half* __restrict__ src, float* __restrict__ dst16,
                             const float* __restrict__ W1, const float* __restrict__ b1,
                             const float* __restrict__ W2, const float* __restrict__ b2, int n) {
    __shared__ float W1s[F * F];
    __shared__ float W2s[F * FO];
    __shared__ float b2s[FO];
    __shared__ float y_s[32][F + PAD];
    __shared__ float h_s[32][F + PAD];
    for (int t = threadIdx.x; t < F * F; t += blockDim.x) W1s[t] = W1[t];
    for (int t = threadIdx.x; t < F * FO; t += blockDim.x) W2s[t] = W2[t];
    if (threadIdx.x < FO) b2s[threadIdx.x] = b2[threadIdx.x];
    __syncthreads();

    int nodeL = threadIdx.x >> 3;
    int l8    = threadIdx.x & 7;
    int node  = blockIdx.x * 32 + nodeL;

    float acc[8];
    #pragma unroll
    for (int i = 0; i < 8; i++) acc[i] = 0.f;
    float d = 0.f;
    if (node < n) {
        gather_row_h(src, node, l8, acc);
        d = g_dinv[node];                  // y4 = dinv * (u_i + sum u_j)
        #pragma unroll
        for (int i = 0; i < 8; i++) acc[i] *= d;
    }
    ((float4*)&y_s[nodeL][8 * l8])[0]     = make_float4(acc[0], acc[1], acc[2], acc[3]);
    ((float4*)&y_s[nodeL][8 * l8 + 4])[0] = make_float4(acc[4], acc[5], acc[6], acc[7]);
    __syncwarp();

    // GEMM1 + SELU: lane l8 computes features l8 + 8*m, m=0..7
    float h[8];
    #pragma unroll
    for (int m = 0; m < 8; m++) h[m] = b1[l8 + 8 * m];
    #pragma unroll 8
    for (int k = 0; k < F; k++) {
        float yk = y_s[nodeL][k];
        #pragma unroll
        for (int m = 0; m < 8; m++)
            h[m] += yk * W1s[k * F + l8 + 8 * m];
    }
    const float al = 1.6732632423543772f, sc = 1.0507009873554805f;
    #pragma unroll
    for (int m = 0; m < 8; m++) {
        h[m] = (h[m] > 0.f) ? sc * h[m] : sc * al * expm1f(h[m]);
        h_s[nodeL][l8 + 8 * m] = h[m];
    }
    __syncwarp();

    // GEMM2: lane l8 computes output features l8 and l8+8; store z~ = dinv*z
    float z0 = b2s[l8], z1 = b2s[l8 + 8];
    #pragma unroll 8
    for (int k = 0; k < F; k++) {
        float hk = h_s[nodeL][k];
        z0 += hk * W2s[k * FO + l8];
        z1 += hk * W2s[k * FO + l8 + 8];
    }
    if (node < n) {
        dst16[(size_t)node * FO + l8]     = z0 * d;
        dst16[(size_t)node * FO + l8 + 8] = z1 * d;
    }
}

// ---------------- final hop + log_softmax: out = dinv*(z~_i + sum z~_j) ------
__global__ void k_hop16(const float* __restrict__ src16, float* __restrict__ out, int n) {
    int tid  = blockIdx.x * blockDim.x + threadIdx.x;
    int node = tid >> 2;
    int l4   = tid & 3;
    if (node >= n) return;
    float4 a = ((const float4*)(src16 + (size_t)node * FO))[l4];
    float4 acc = a;
    int s = g_rowptr[node], e = g_rowptr[node + 1];
    for (int p = s; p < e; p += 4) {
        int4 c = *(const int4*)(g_col + p);
        float4 v0 = ((const float4*)(src16 + (size_t)c.x * FO))[l4];
        float4 v1 = ((const float4*)(src16 + (size_t)c.y * FO))[l4];
        float4 v2 = ((const float4*)(src16 + (size_t)c.z * FO))[l4];
        float4 v3 = ((const float4*)(src16 + (size_t)c.w * FO))[l4];
        acc.x += v0.x + v1.x + v2.x + v3.x;
        acc.y += v0.y + v1.y + v2.y + v3.y;
        acc.z += v0.z + v1.z + v2.z + v3.z;
        acc.w += v0.w + v1.w + v2.w + v3.w;
    }
    float d = g_dinv[node];
    acc.x *= d; acc.y *= d; acc.z *= d; acc.w *= d;

    float m = fmaxf(fmaxf(acc.x, acc.y), fmaxf(acc.z, acc.w));
    m = fmaxf(m, __shfl_xor_sync(0xffffffffu, m, 1, 4));
    m = fmaxf(m, __shfl_xor_sync(0xffffffffu, m, 2, 4));
    float ssum = expf(acc.x - m) + expf(acc.y - m) + expf(acc.z - m) + expf(acc.w - m);
    ssum += __shfl_xor_sync(0xffffffffu, ssum, 1, 4);
    ssum += __shfl_xor_sync(0xffffffffu, ssum, 2, 4);
    float lse = m + logf(ssum);
    float4 r = make_float4(acc.x - lse, acc.y - lse, acc.z - lse, acc.w - lse);
    ((float4*)(out + (size_t)node * FO))[l4] = r;
}

// ---------------- launch ----------------
extern "C" void kernel_launch(void* const* d_in, const int* in_sizes, int n_in,
                              void* d_out, int out_size) {
    const float* x  = (const float*)d_in[0];
    const float* W1 = (const float*)d_in[1];
    const float* b1 = (const float*)d_in[2];
    const float* W2 = (const float*)d_in[3];
    const float* b2 = (const float*)d_in[4];
    const int*   ei = (const int*)  d_in[5];
    int N = in_sizes[0] / F;
    int E = in_sizes[5] / 2;
    float* out = (float*)d_out;

    __half *H1, *H2;
    float  *buf16;
    cudaGetSymbolAddress((void**)&H1, g_bufH1);
    cudaGetSymbolAddress((void**)&H2, g_bufH2);
    cudaGetSymbolAddress((void**)&buf16, g_buf16);

    int tb = 256;
    int total4 = N * F / 4;
    int nbCH   = ((total4 > E ? total4 : E) + tb - 1) / tb;
    int nFill  = (E > N * 8 ? E : N * 8);
    int nbFill = (nFill + tb - 1) / tb;
    int nb1024 = (N + 1023) / 1024;
    int nb8    = (N * 8 + tb - 1) / tb;
    int nbF    = (N + 31) / 32;
    int nbQ    = (N * 4 + tb - 1) / tb;

    // fused convert + histogram/rank (hist is 0 on entry by invariant)
    k_cvt_hist  <<<nbCH, tb>>>(x, total4, ei, E, N);
    // padded CSR build (col-only) + u = dinv*x scaling + hist re-zero
    k_scan_block<<<nb1024, 1024>>>(N);
    k_scan_add  <<<nb1024, 1024>>>(N);
    k_fill      <<<nbFill, tb>>>(ei, E, N);

    // 3 unweighted gather-sum hops, then hop4 fused with GEMM1+SELU+GEMM2
    k_spmm_h<<<nb8, tb>>>(H1, H2, N);
    k_spmm_h<<<nb8, tb>>>(H2, H1, N);
    k_spmm_h<<<nb8, tb>>>(H1, H2, N);
    k_hop4_fused<<<nbF, tb>>>(H2, buf16, W1, b1, W2, b2, N);

    // conv2: unweighted 16-wide hop + log_softmax
    k_hop16<<<nbQ, tb>>>(buf16, out, N);
}

// round 17
// speedup vs baseline: 1.2290x; 1.0339x over previous
#include <cuda_runtime.h>
#include <cuda_fp16.h>
#include <math.h>

#define NMAX 100000
#define EMAX 1000000
#define F    64
#define FO   16
// padded CSR: each row rounded up to multiple of 8 with dummy cols -> zero row N
#define EPADMAX (EMAX + 8 * NMAX)

// ---------------- scratch (no allocations allowed) ----------------
// g_hist and g_total are zero on load (BSS) and re-zeroed at the end of k_fill.
__device__ int    g_hist[NMAX];
__device__ int    g_rank[EMAX];
__device__ int    g_rowA[NMAX];          // row start (atomic-allocated)
__device__ int    g_rowB[NMAX];          // row end (padded)
__device__ int    g_col[EPADMAX];        // col only; no weights
__device__ float  g_dinv[NMAX];
__device__ int    g_total;
__device__ __half g_bufH1[(size_t)(NMAX + 1) * F];   // +1: zero dummy row
__device__ __half g_bufH2[(size_t)(NMAX + 1) * F];
__device__ __half g_bufZ[(size_t)(NMAX + 1) * FO];   // fp16 logits z~
// ---------------- fused: x fp32->fp16 convert + edge histogram/rank ----------
// also zeroes the dummy row N of the feature buffers
__global__ void k_cvt_hist(const float* __restrict__ x, int total4,
                           const int* __restrict__ ei, int E, int n) {
    int i = blockIdx.x * blockDim.x + threadIdx.x;
    if (i < E) g_rank[i] = atomicAdd(&g_hist[ei[i]], 1);
    if (i < 16) {
        ((uint2*)(g_bufH1 + (size_t)n * F))[i] = make_uint2(0, 0);
        ((uint2*)(g_bufH2 + (size_t)n * F))[i] = make_uint2(0, 0);
        if (i < 4) ((uint2*)(g_bufZ + (size_t)n * FO))[i] = make_uint2(0, 0);
    }
    if (i >= total4) return;
    float4 v = ((const float4*)x)[i];
    __half2 lo = __floats2half2_rn(v.x, v.y);
    __half2 hi = __floats2half2_rn(v.z, v.w);
    uint2 u;
    u.x = *(unsigned*)&lo; u.y = *(unsigned*)&hi;
    ((uint2*)g_bufH1)[i] = u;
}

// ---------------- row allocation: dinv + padded-range atomic alloc -----------
// warp-aggregated: one global atomicAdd per warp
__global__ void k_alloc(int n) {
    int i = blockIdx.x * blockDim.x + threadIdx.x;
    int lane = threadIdx.x & 31;
    int deg = (i < n) ? g_hist[i] : 0;
    if (i < n) g_dinv[i] = rsqrtf((float)deg + 1.0f);   // +1 self loop
    int vp = (i < n) ? ((deg + 7) & ~7) : 0;            // pad to multiple of 8
    int incl = vp;
    #pragma unroll
    for (int off = 1; off < 32; off <<= 1) {
        int t = __shfl_up_sync(0xffffffffu, incl, off);
        if (lane >= off) incl += t;
    }
    int base = 0;
    if (lane == 31) base = atomicAdd(&g_total, incl);
    base = __shfl_sync(0xffffffffu, base, 31);
    if (i < n) {
        int start = base + incl - vp;
        g_rowA[i] = start;
        g_rowB[i] = start + vp;
    }
}

// fill (atomic-free, col only) + dummy padding + u = dinv*x scaling + invariants
__global__ void k_fill(const int* __restrict__ ei, int E, int n) {
    int e = blockIdx.x * blockDim.x + threadIdx.x;
    if (e == 0) g_total = 0;              // restore invariant for next launch
    if (e < n * 8) {                      // scale H1 in place: u = dinv * x
        int node = e >> 3;
        float dv = g_dinv[node];
        uint4 u = ((uint4*)g_bufH1)[e];
        __half2* h = (__half2*)&u;
        #pragma unroll
        for (int k = 0; k < 4; k++) {
            float2 f = __half22float2(h[k]);
            h[k] = __floats2half2_rn(f.x * dv, f.y * dv);
        }
        ((uint4*)g_bufH1)[e] = u;
    }
    if (e < n) {                          // dummy padding -> zero row n
        int deg = g_hist[e];
        int st = g_rowA[e] + deg;
        int en = g_rowB[e];
        for (int p = st; p < en; p++) g_col[p] = n;
        g_hist[e] = 0;                    // restore invariant for next launch
    }
    if (e >= E) return;
    int r = ei[e];
    int c = ei[E + e];
    g_col[g_rowA[r] + g_rank[e]] = c;
}

// ---------------- fp16 gather-sum core: 8 lanes/node, 8 features per lane ----
__device__ __forceinline__ void h8_add(uint4 u, float* acc) {
    __half2* h = (__half2*)&u;
    float2 f0 = __half22float2(h[0]);
    float2 f1 = __half22float2(h[1]);
    float2 f2 = __half22float2(h[2]);
    float2 f3 = __half22float2(h[3]);
    acc[0] += f0.x; acc[1] += f0.y;
    acc[2] += f1.x; acc[3] += f1.y;
    acc[4] += f2.x; acc[5] += f2.y;
    acc[6] += f3.x; acc[7] += f3.y;
}

// acc = u_self + sum(u_neighbors); caller applies the dinv power
__device__ __forceinline__ void gather_row_h(const __half* __restrict__ src, int node,
                                             int l8, float* acc) {
    #pragma unroll
    for (int i = 0; i < 8; i++) acc[i] = 0.f;
    h8_add(((const uint4*)(src + (size_t)node * F))[l8], acc);
    int s = g_rowA[node], e = g_rowB[node];
    for (int p = s; p < e; p += 8) {      // ranges are multiples of 8; int4-aligned
        int4 c0 = *(const int4*)(g_col + p);
        int4 c1 = *(const int4*)(g_col + p + 4);
        uint4 v0 = ((const uint4*)(src + (size_t)c0.x * F))[l8];
        uint4 v1 = ((const uint4*)(src + (size_t)c0.y * F))[l8];
        uint4 v2 = ((const uint4*)(src + (size_t)c0.z * F))[l8];
        uint4 v3 = ((const uint4*)(src + (size_t)c0.w * F))[l8];
        uint4 v4 = ((const uint4*)(src + (size_t)c1.x * F))[l8];
        uint4 v5 = ((const uint4*)(src + (size_t)c1.y * F))[l8];
        uint4 v6 = ((const uint4*)(src + (size_t)c1.z * F))[l8];
        uint4 v7 = ((const uint4*)(src + (size_t)c1.w * F))[l8];
        h8_add(v0, acc); h8_add(v1, acc); h8_add(v2, acc); h8_add(v3, acc);
        h8_add(v4, acc); h8_add(v5, acc); h8_add(v6, acc); h8_add(v7, acc);
    }
}

__device__ __forceinline__ uint4 f8_to_h8(const float* acc) {
    __half2 h0 = __floats2half2_rn(acc[0], acc[1]);
    __half2 h1 = __floats2half2_rn(acc[2], acc[3]);
    __half2 h2 = __floats2half2_rn(acc[4], acc[5]);
    __half2 h3 = __floats2half2_rn(acc[6], acc[7]);
    uint4 u;
    u.x = *(unsigned*)&h0; u.y = *(unsigned*)&h1;
    u.z = *(unsigned*)&h2; u.w = *(unsigned*)&h3;
    return u;
}

// hops 1-3: u' = dinv^2 * (u_i + sum u_j)
__global__ void k_spmm_h(const __half* __restrict__ src, __half* __restrict__ dst, int n) {
    int tid  = blockIdx.x * blockDim.x + threadIdx.x;
    int node = tid >> 3;
    int l8   = tid & 7;
    if (node >= n) return;
    float acc[8];
    gather_row_h(src, node, l8, acc);
    float d = g_dinv[node];
    float sw = d * d;
    #pragma unroll
    for (int i = 0; i < 8; i++) acc[i] *= sw;
    ((uint4*)(dst + (size_t)node * F))[l8] = f8_to_h8(acc);
}

// ---------------- hop4 fused: gather + W1 + SELU + W2 -> z~ = dinv*z (fp16) --
#define PAD 4
__global__ void k_hop4_fused(const __half* __restrict__ src, __half* __restrict__ dstZ,
                             const float* __restrict__ W1, const float* __restrict__ b1,
                             const float* __restrict__ W2, const float* __restrict__ b2, int n) {
    __shared__ float W1s[F * F];
    __shared__ float W2s[F * FO];
    __shared__ float b2s[FO];
    __shared__ float y_s[32][F + PAD];
    __shared__ float h_s[32][F + PAD];
    for (int t = threadIdx.x; t < F * F; t += blockDim.x) W1s[t] = W1[t];
    for (int t = threadIdx.x; t < F * FO; t += blockDim.x) W2s[t] = W2[t];
    if (threadIdx.x < FO) b2s[threadIdx.x] = b2[threadIdx.x];
    __syncthreads();

    int nodeL = threadIdx.x >> 3;
    int l8    = threadIdx.x & 7;
    int node  = blockIdx.x * 32 + nodeL;

    float acc[8];
    #pragma unroll
    for (int i = 0; i < 8; i++) acc[i] = 0.f;
    float d = 0.f;
    if (node < n) {
        gather_row_h(src, node, l8, acc);
        d = g_dinv[node];                  // y4 = dinv * (u_i + sum u_j)
        #pragma unroll
        for (int i = 0; i < 8; i++) acc[i] *= d;
    }
    ((float4*)&y_s[nodeL][8 * l8])[0]     = make_float4(acc[0], acc[1], acc[2], acc[3]);
    ((float4*)&y_s[nodeL][8 * l8 + 4])[0] = make_float4(acc[4], acc[5], acc[6], acc[7]);
    __syncwarp();

    // GEMM1 + SELU: lane l8 computes features l8 + 8*m, m=0..7
    float h[8];
    #pragma unroll
    for (int m = 0; m < 8; m++) h[m] = b1[l8 + 8 * m];
    #pragma unroll 8
    for (int k = 0; k < F; k++) {
        float yk = y_s[nodeL][k];
        #pragma unroll
        for (int m = 0; m < 8; m++)
            h[m] += yk * W1s[k * F + l8 + 8 * m];
    }
    const float al = 1.6732632423543772f, sc = 1.0507009873554805f;
    #pragma unroll
    for (int m = 0; m < 8; m++) {
        h[m] = (h[m] > 0.f) ? sc * h[m] : sc * al * expm1f(h[m]);
        h_s[nodeL][l8 + 8 * m] = h[m];
    }
    __syncwarp();

    // GEMM2: lane l8 computes output features l8 and l8+8; store z~ = dinv*z fp16
    float z0 = b2s[l8], z1 = b2s[l8 + 8];
    #pragma unroll 8
    for (int k = 0; k < F; k++) {
        float hk = h_s[nodeL][k];
        z0 += hk * W2s[k * FO + l8];
        z1 += hk * W2s[k * FO + l8 + 8];
    }
    if (node < n) {
        dstZ[(size_t)node * FO + l8]     = __float2half_rn(z0 * d);
        dstZ[(size_t)node * FO + l8 + 8] = __float2half_rn(z1 * d);
    }
}

// ---------------- final hop + log_softmax: out = dinv*(z~_i + sum z~_j) ------
// fp16 z~ gather: 4 lanes/node, uint2 (4 halves) per lane
__global__ void k_hop16(const __half* __restrict__ srcZ, float* __restrict__ out, int n) {
    int tid  = blockIdx.x * blockDim.x + threadIdx.x;
    int node = tid >> 2;
    int l4   = tid & 3;
    if (node >= n) return;

    uint2 a = ((const uint2*)(srcZ + (size_t)node * FO))[l4];
    __half2* ah = (__half2*)&a;
    float2 a0 = __half22float2(ah[0]);
    float2 a1 = __half22float2(ah[1]);
    float4 acc = make_float4(a0.x, a0.y, a1.x, a1.y);

    int s = g_rowA[node], e = g_rowB[node];
    for (int p = s; p < e; p += 4) {
        int4 c = *(const int4*)(g_col + p);
        uint2 u0 = ((const uint2*)(srcZ + (size_t)c.x * FO))[l4];
        uint2 u1 = ((const uint2*)(srcZ + (size_t)c.y * FO))[l4];
        uint2 u2 = ((const uint2*)(srcZ + (size_t)c.z * FO))[l4];
        uint2 u3 = ((const uint2*)(srcZ + (size_t)c.w * FO))[l4];
        __half2* h0 = (__half2*)&u0; __half2* h1 = (__half2*)&u1;
        __half2* h2 = (__half2*)&u2; __half2* h3 = (__half2*)&u3;
        float2 f;
        f = __half22float2(h0[0]); acc.x += f.x; acc.y += f.y;
        f = __half22float2(h0[1]); acc.z += f.x; acc.w += f.y;
        f = __half22float2(h1[0]); acc.x += f.x; acc.y += f.y;
        f = __half22float2(h1[1]); acc.z += f.x; acc.w += f.y;
        f = __half22float2(h2[0]); acc.x += f.x; acc.y += f.y;
        f = __half22float2(h2[1]); acc.z += f.x; acc.w += f.y;
        f = __half22float2(h3[0]); acc.x += f.x; acc.y += f.y;
        f = __half22float2(h3[1]); acc.z += f.x; acc.w += f.y;
    }
    float d = g_dinv[node];
    acc.x *= d; acc.y *= d; acc.z *= d; acc.w *= d;

    float m = fmaxf(fmaxf(acc.x, acc.y), fmaxf(acc.z, acc.w));
    m = fmaxf(m, __shfl_xor_sync(0xffffffffu, m, 1, 4));
    m = fmaxf(m, __shfl_xor_sync(0xffffffffu, m, 2, 4));
    float ssum = expf(acc.x - m) + expf(acc.y - m) + expf(acc.z - m) + expf(acc.w - m);
    ssum += __shfl_xor_sync(0xffffffffu, ssum, 1, 4);
    ssum += __shfl_xor_sync(0xffffffffu, ssum, 2, 4);
    float lse = m + logf(ssum);
    float4 r = make_float4(acc.x - lse, acc.y - lse, acc.z - lse, acc.w - lse);
    ((float4*)(out + (size_t)node * FO))[l4] = r;
}

// ---------------- launch ----------------
extern "C" void kernel_launch(void* const* d_in, const int* in_sizes, int n_in,
                              void* d_out, int out_size) {
    const float* x  = (const float*)d_in[0];
    const float* W1 = (const float*)d_in[1];
    const float* b1 = (const float*)d_in[2];
    const float* W2 = (const float*)d_in[3];
    const float* b2 = (const float*)d_in[4];
    const int*   ei = (const int*)  d_in[5];
    int N = in_sizes[0] / F;
    int E = in_sizes[5] / 2;
    float* out = (float*)d_out;

    __half *H1, *H2, *Z;
    cudaGetSymbolAddress((void**)&H1, g_bufH1);
    cudaGetSymbolAddress((void**)&H2, g_bufH2);
    cudaGetSymbolAddress((void**)&Z,  g_bufZ);

    int tb = 256;
    int total4 = N * F / 4;
    int nbCH   = ((total4 > E ? total4 : E) + tb - 1) / tb;
    int nFill  = (E > N * 8 ? E : N * 8);
    int nbFill = (nFill + tb - 1) / tb;
    int nbA    = (N + tb - 1) / tb;
    int nb8    = (N * 8 + tb - 1) / tb;
    int nbF    = (N + 31) / 32;
    int nbQ    = (N * 4 + tb - 1) / tb;

    // fused convert + histogram/rank (hist/total are 0 on entry by invariant)
    k_cvt_hist<<<nbCH, tb>>>(x, total4, ei, E, N);
    // row allocation (atomic, warp-aggregated) + fill + padding + scaling
    k_alloc   <<<nbA, tb>>>(N);
    k_fill    <<<nbFill, tb>>>(ei, E, N);

    // 3 unweighted gather-sum hops, then hop4 fused with GEMM1+SELU+GEMM2
    k_spmm_h<<<nb8, tb>>>(H1, H2, N);
    k_spmm_h<<<nb8, tb>>>(H2, H1, N);
    k_spmm_h<<<nb8, tb>>>(H1, H2, N);
    k_hop4_fused<<<nbF, tb>>>(H2, Z, W1, b1, W2, b2, N);

    // conv2: unweighted fp16 hop + log_softmax
    k_hop16<<<nbQ, tb>>>(Z, out, N);
}